// round 9
// baseline (speedup 1.0000x reference)
#include <cuda_runtime.h>
#include <cstdint>

#define BATCH 64
#define SEQ   4096
#define LBL   128
#define IGN   (-100)
#define NACC  512
#define NBLK  ((BATCH * SEQ) / 64)   // 4096 loss blocks, 64 tokens each

// Statically initialized so the first (correctness) run is valid without an
// init kernel. The last loss block restores all state after each launch.
#define R8 SEQ, SEQ, SEQ, SEQ, SEQ, SEQ, SEQ, SEQ
__device__ int g_first_invalid[BATCH] = {R8, R8, R8, R8, R8, R8, R8, R8};
#undef R8
__device__ double   g_acc[NACC];       // zero-init; self-resetting
__device__ unsigned g_done = 0;        // block-completion counter; self-resetting

// Full-chip scan over target (4 MB): 256 blocks x 256 threads, 4 tokens/thread.
__global__ __launch_bounds__(256) void scan_kernel(const int* __restrict__ target) {
    const int base = blockIdx.x * 1024 + threadIdx.x;
    const int4* tg = reinterpret_cast<const int4*>(target);
#pragma unroll
    for (int i = 0; i < 4; i++) {
        const int token = base + i * 256;
        const int4 t = tg[token];
        if (t.x == IGN || t.y == IGN || t.z == IGN || t.w == IGN)
            atomicMin(&g_first_invalid[token >> 12], token & (SEQ - 1));
    }
}

// 8 tokens per warp (two groups of 4), 8 lanes per token.
// __launch_bounds__(256, 4) -> 64-reg budget so all 10 loads stay in flight.
__global__ __launch_bounds__(256, 4) void loss_kernel(
    const float* __restrict__ emit,
    const int*   __restrict__ target,
    float*       __restrict__ out)
{
    const int warp   = threadIdx.x >> 5;
    const int lane   = threadIdx.x & 31;
    const int tg     = lane >> 3;        // token-in-group 0..3
    const int g      = lane & 7;         // lane-in-token 0..7
    const int token0 = blockIdx.x * 64 + warp * 8 + tg;
    const int token1 = token0 + 4;
    const int b      = token0 >> 12;     // whole block is one batch row
    const int s0     = token0 & (SEQ - 1);
    const int s1     = token1 & (SEQ - 1);

    // Targets first: starts the gather dependency chain early (L2-hot).
    int t0 = 0, t1 = 0;
    if (g < 4) {
        t0 = target[token0 * 4 + g] & (LBL - 1);
        t1 = target[token1 * 4 + g] & (LBL - 1);
    }

    // 8 independent 16B loads, all live simultaneously (64-reg budget).
    const float4* row0 = reinterpret_cast<const float4*>(emit + (size_t)token0 * LBL);
    const float4* row1 = reinterpret_cast<const float4*>(emit + (size_t)token1 * LBL);
    const float4 a0 = row0[g],      a1 = row0[8 + g];
    const float4 a2 = row0[16 + g], a3 = row0[24 + g];
    const float4 c0 = row1[g],      c1 = row1[8 + g];
    const float4 c2 = row1[16 + g], c3 = row1[24 + g];

    // Gathers (hit-under-miss merges with the in-flight row lines).
    float g0 = 0.0f, g1 = 0.0f;
    if (g < 4) {
        g0 = emit[(size_t)token0 * LBL + t0];
        g1 = emit[(size_t)token1 * LBL + t1];
    }
    float st0 = (g < 4) ? __expf(g0) : 0.0f;
    float st1 = (g < 4) ? __expf(g1) : 0.0f;

    float se0 = 0.0f, se1 = 0.0f;
#define PASS(ACC, V)                                                \
    {                                                               \
        const float e0 = __expf(V.x), e1 = __expf(V.y),             \
                    e2 = __expf(V.z), e3 = __expf(V.w);             \
        ACC += (e0 + e1) + (e2 + e3);                               \
    }
    PASS(se0, a0) PASS(se0, a1) PASS(se0, a2) PASS(se0, a3)
    PASS(se1, c0) PASS(se1, c1) PASS(se1, c2) PASS(se1, c3)
#undef PASS

    // Reduce within the 8-lane group (offsets 1,2,4 stay inside the group).
#pragma unroll
    for (int o = 1; o <= 4; o <<= 1) {
        se0 += __shfl_xor_sync(0xffffffffu, se0, o);
        st0 += __shfl_xor_sync(0xffffffffu, st0, o);
        se1 += __shfl_xor_sync(0xffffffffu, se1, o);
        st1 += __shfl_xor_sync(0xffffffffu, st1, o);
    }

    __shared__ float part[32];
    __shared__ bool  amLast;
    if (g == 0) {
        const int fi = g_first_invalid[b];
        float loss;
        if (s1 < fi)        // both tokens valid (common case): 2 logs not 4
            loss = __logf(se0 * se1) - __logf(st0 * st1);
        else if (s0 < fi)
            loss = __logf(se0) - __logf(st0);
        else
            loss = 0.0f;
        part[warp * 4 + tg] = loss;
    }
    __syncthreads();

    if (threadIdx.x < 32) {
        float x = part[threadIdx.x];
#pragma unroll
        for (int o = 16; o; o >>= 1) x += __shfl_xor_sync(0xffffffffu, x, o);
        if (threadIdx.x == 0) {
            atomicAdd(&g_acc[blockIdx.x & (NACC - 1)], (double)x);
            __threadfence();
            amLast = (atomicAdd(&g_done, 1u) == NBLK - 1);
        }
    }
    __syncthreads();

    // Last block: global reduce + restore all state for the next replay.
    if (amLast) {
        const int i = threadIdx.x;                     // 256 threads
        double x = g_acc[i] + g_acc[i + 256];
        g_acc[i] = 0.0;
        g_acc[i + 256] = 0.0;
        if (i < BATCH) g_first_invalid[i] = SEQ;
        if (i == 0) g_done = 0;

        __shared__ double wsum[8];
#pragma unroll
        for (int o = 16; o; o >>= 1) x += __shfl_xor_sync(0xffffffffu, x, o);
        if ((i & 31) == 0) wsum[i >> 5] = x;
        __syncthreads();
        if (i == 0) {
            double sum = 0.0;
#pragma unroll
            for (int w = 0; w < 8; w++) sum += wsum[w];
            out[0] = (float)sum;
        }
    }
}

extern "C" void kernel_launch(void* const* d_in, const int* in_sizes, int n_in,
                              void* d_out, int out_size)
{
    const float* emit   = (const float*)d_in[0];
    const int*   target = (const int*)d_in[1];
    float*       out    = (float*)d_out;

    scan_kernel<<<256, 256>>>(target);
    loss_kernel<<<NBLK, 256>>>(emit, target, out);
}